// round 1
// baseline (speedup 1.0000x reference)
#include <cuda_runtime.h>
#include <math.h>

// ---------------------------------------------------------------------------
// AcidSynth: osc -> time-varying RBJ lowpass biquad (DF2T) -> tanh
// Parallelized via blocked affine scan over the 2-state linear recurrence.
// ---------------------------------------------------------------------------

#define N_SAMP   524288
#define CHUNK    256
#define NCHUNK   (N_SAMP / CHUNK)   // 2048
#define L2_FAN   32
#define L2_N     (NCHUNK / L2_FAN)  // 64

#define TWO_PI_F 6.28318530717958647692f
#define ENV_LEN  6000.0f            // NOTE_ON_DUR * SR

// Scratch (device globals: no allocations allowed)
__device__ float4 g_T[N_SAMP];      // {b0n, a1n, a2n, dry}

struct ChunkT { float m00, m01, m10, m11, c1, c2; };
__device__ ChunkT g_CT[NCHUNK];     // per-chunk composed affine transform
__device__ float2 g_S[NCHUNK];      // state at start of each chunk

// ---------------------------------------------------------------------------
// K1: fully parallel per-sample coefficient + dry-signal precompute
// ---------------------------------------------------------------------------
__global__ void k_coeffs(const float* __restrict__ w_sig,
                         const float* __restrict__ q_sig,
                         const float* __restrict__ midi01,
                         const float* __restrict__ alpha01,
                         const float* __restrict__ phase)
{
    int t = blockIdx.x * blockDim.x + threadIdx.x;
    if (t >= N_SAMP) return;
    float tf = (float)t;

    // --- per-sample RBJ lowpass coefficients (normalized by a0) ---
    float w_hz = w_sig[t] * 7900.0f + 100.0f;
    float qv   = q_sig[t] * (8.0f - 0.7071f) + 0.7071f;
    float w0   = (TWO_PI_F * w_hz) / 48000.0f;
    float sw, cw;
    sincosf(w0, &sw, &cw);
    float af = sw / (2.0f * qv);
    float a0 = 1.0f + af;
    float b0 = ((1.0f - cw) * 0.5f) / a0;
    float a1 = (-2.0f * cw) / a0;
    float a2 = (1.0f - af) / a0;

    // --- dry synth signal: nonzero only while the note-on envelope lives ---
    float dry = 0.0f;
    if (t < 6000) {
        float alpha = alpha01[0] * (3.0f - 0.2f) + 0.2f;
        float midi  = rintf(midi01[0] * (60.0f - 30.0f) + 30.0f);  // round-half-even like jnp.round
        float f0    = 440.0f * exp2f((midi - 69.0f) / 12.0f);
        float eb    = 1.0f - tf / ENV_LEN;
        eb          = fminf(fmaxf(eb, 0.0f), 1.0f);
        float env   = powf(eb, alpha);
        float arg   = phase[0] + (TWO_PI_F * f0) * tf / 48000.0f;
        float u     = arg / TWO_PI_F;
        float ph    = u - floorf(u);
        float sq    = (ph < 0.5f) ? 1.0f : -1.0f;
        // OSC_SHAPE == 1.0 -> pure square; OSC_GAIN = 0.5
        dry = (0.5f * sq) * env;
    }

    g_T[t] = make_float4(b0, a1, a2, dry);
}

// ---------------------------------------------------------------------------
// K2: per-chunk sequential composition of the per-sample affine maps.
//   state map: s' = A_t s + c_t,  A_t = [[-a1, 1], [-a2, 0]],
//   c_t = [(b1 - a1 b0) x, (b2 - a2 b0) x], with b1 = 2 b0, b2 = b0, x = dry
// ---------------------------------------------------------------------------
__global__ void k_compose()
{
    int k = blockIdx.x * blockDim.x + threadIdx.x;
    if (k >= NCHUNK) return;
    int base = k * CHUNK;

    float m00 = 1.0f, m01 = 0.0f, m10 = 0.0f, m11 = 1.0f;
    float c1 = 0.0f, c2 = 0.0f;

#pragma unroll 4
    for (int i = 0; i < CHUNK; i++) {
        float4 T = g_T[base + i];
        float b0 = T.x, a1 = T.y, a2 = T.z, x = T.w;
        float cx1 = (2.0f * b0 - a1 * b0) * x;
        float cx2 = (b0 - a2 * b0) * x;
        // M' = A_t * M ; c' = A_t * c + c_t
        float n00 = fmaf(-a1, m00, m10);
        float n01 = fmaf(-a1, m01, m11);
        float n10 = -a2 * m00;
        float n11 = -a2 * m01;
        float nc1 = fmaf(-a1, c1, c2) + cx1;
        float nc2 = fmaf(-a2, c1, cx2);
        m00 = n00; m01 = n01; m10 = n10; m11 = n11;
        c1 = nc1; c2 = nc2;
    }

    ChunkT out;
    out.m00 = m00; out.m01 = m01; out.m10 = m10; out.m11 = m11;
    out.c1 = c1;  out.c2 = c2;
    g_CT[k] = out;
}

// ---------------------------------------------------------------------------
// K3: hierarchical scan over the 2048 chunk transforms (single block).
//   64 threads each compose 32 transforms; thread 0 scans the 64 supers;
//   then each thread replays its 32 to emit per-chunk start states.
// ---------------------------------------------------------------------------
__global__ void k_scan(const float* __restrict__ zi)
{
    __shared__ float  sm[L2_N][6];
    __shared__ float2 ss[L2_N];

    int j = threadIdx.x;  // 0..63

    // compose 32 general affine maps: (T ∘ acc): M' = T.M * M ; c' = T.M*c + T.c
    float m00 = 1.0f, m01 = 0.0f, m10 = 0.0f, m11 = 1.0f;
    float c1 = 0.0f, c2 = 0.0f;
    for (int i = 0; i < L2_FAN; i++) {
        ChunkT T = g_CT[j * L2_FAN + i];
        float n00 = T.m00 * m00 + T.m01 * m10;
        float n01 = T.m00 * m01 + T.m01 * m11;
        float n10 = T.m10 * m00 + T.m11 * m10;
        float n11 = T.m10 * m01 + T.m11 * m11;
        float nc1 = T.m00 * c1 + T.m01 * c2 + T.c1;
        float nc2 = T.m10 * c1 + T.m11 * c2 + T.c2;
        m00 = n00; m01 = n01; m10 = n10; m11 = n11;
        c1 = nc1; c2 = nc2;
    }
    sm[j][0] = m00; sm[j][1] = m01; sm[j][2] = m10;
    sm[j][3] = m11; sm[j][4] = c1;  sm[j][5] = c2;
    __syncthreads();

    if (j == 0) {
        float s1 = zi[0], s2 = zi[1];
        for (int i = 0; i < L2_N; i++) {
            ss[i] = make_float2(s1, s2);
            float t1 = sm[i][0] * s1 + sm[i][1] * s2 + sm[i][4];
            float t2 = sm[i][2] * s1 + sm[i][3] * s2 + sm[i][5];
            s1 = t1; s2 = t2;
        }
    }
    __syncthreads();

    float s1 = ss[j].x, s2 = ss[j].y;
    for (int i = 0; i < L2_FAN; i++) {
        int k = j * L2_FAN + i;
        g_S[k] = make_float2(s1, s2);
        ChunkT T = g_CT[k];
        float t1 = T.m00 * s1 + T.m01 * s2 + T.c1;
        float t2 = T.m10 * s1 + T.m11 * s2 + T.c2;
        s1 = t1; s2 = t2;
    }
}

// ---------------------------------------------------------------------------
// K4: per-chunk replay with the exact reference DF2T step order + tanh.
// ---------------------------------------------------------------------------
__global__ void k_replay(float* __restrict__ out)
{
    int k = blockIdx.x * blockDim.x + threadIdx.x;
    if (k >= NCHUNK) return;
    int base = k * CHUNK;

    float2 s = g_S[k];
    float s1 = s.x, s2 = s.y;

#pragma unroll 4
    for (int i = 0; i < CHUNK; i++) {
        float4 T = g_T[base + i];
        float b0 = T.x, a1 = T.y, a2 = T.z, x = T.w;
        float p0 = b0 * x;                       // b0*xt   (b1*xt = 2*p0, b2*xt = p0)
        float y  = p0 + s1;                      // y = b0*xt + s1
        float ns1 = fmaf(-a1, y, 2.0f * p0) + s2;// s1 = b1*xt - a1*y + s2
        float ns2 = fmaf(-a2, y, p0);            // s2 = b2*xt - a2*y
        s1 = ns1; s2 = ns2;
        out[base + i] = tanhf(y);                // DIST_GAIN = 1
    }
}

// ---------------------------------------------------------------------------
// Inputs (metadata order): x, midi_f0_0to1, alpha_0to1, w_mod_sig, q_mod_sig,
//                          phase, zi. Output: wet [1, N] float32.
// ---------------------------------------------------------------------------
extern "C" void kernel_launch(void* const* d_in, const int* in_sizes, int n_in,
                              void* d_out, int out_size)
{
    const float* midi  = (const float*)d_in[1];
    const float* alpha = (const float*)d_in[2];
    const float* w     = (const float*)d_in[3];
    const float* q     = (const float*)d_in[4];
    const float* phase = (const float*)d_in[5];
    const float* zi    = (const float*)d_in[6];
    float* out = (float*)d_out;

    k_coeffs<<<N_SAMP / 256, 256>>>(w, q, midi, alpha, phase);
    k_compose<<<NCHUNK / 256, 256>>>();
    k_scan<<<1, L2_N>>>(zi);
    k_replay<<<NCHUNK / 256, 256>>>(out);
}

// round 2
// speedup vs baseline: 5.9010x; 5.9010x over previous
#include <cuda_runtime.h>
#include <math.h>

// ---------------------------------------------------------------------------
// AcidSynth: osc -> time-varying RBJ lowpass biquad (DF2T) -> tanh
// Blocked affine scan; 8 samples/thread + warp-level ordered map scan.
// ---------------------------------------------------------------------------

#define N_SAMP   524288
#define TPS      8                       // samples per thread
#define NTHREAD  (N_SAMP / TPS)          // 65536
#define WCHUNK   (32 * TPS)              // 256 samples per warp
#define NWARP    (N_SAMP / WCHUNK)       // 2048 warp-chunks

#define TWO_PI_F 6.28318530717958647692f

// Scratch (device globals: no allocations allowed)
__device__ float4 g_T[N_SAMP];           // {b0n, a1n, a2n, dry}

struct Aff { float m00, m01, m10, m11, c1, c2; };
__device__ Aff    g_CT[NWARP];           // per-warp-chunk composed affine map
__device__ float2 g_S[NWARP];            // state at start of each warp-chunk

__device__ __forceinline__ Aff aff_identity() {
    Aff r; r.m00 = 1.f; r.m01 = 0.f; r.m10 = 0.f; r.m11 = 1.f; r.c1 = 0.f; r.c2 = 0.f;
    return r;
}

// g after f  (apply f first):  M = Mg*Mf,  c = Mg*cf + cg
__device__ __forceinline__ Aff aff_compose(const Aff& g, const Aff& f) {
    Aff r;
    r.m00 = g.m00 * f.m00 + g.m01 * f.m10;
    r.m01 = g.m00 * f.m01 + g.m01 * f.m11;
    r.m10 = g.m10 * f.m00 + g.m11 * f.m10;
    r.m11 = g.m10 * f.m01 + g.m11 * f.m11;
    r.c1  = g.m00 * f.c1  + g.m01 * f.c2 + g.c1;
    r.c2  = g.m10 * f.c1  + g.m11 * f.c2 + g.c2;
    return r;
}

// compose one biquad step (A_t, c_t) onto accumulated map (apply acc first)
//   A_t = [[-a1, 1], [-a2, 0]],  c_t = [(2b0 - a1 b0) x, (b0 - a2 b0) x]
__device__ __forceinline__ void aff_step(Aff& m, float b0, float a1, float a2, float x) {
    float cx1 = (2.0f * b0 - a1 * b0) * x;
    float cx2 = (b0 - a2 * b0) * x;
    float n00 = fmaf(-a1, m.m00, m.m10);
    float n01 = fmaf(-a1, m.m01, m.m11);
    float n10 = -a2 * m.m00;
    float n11 = -a2 * m.m01;
    float nc1 = fmaf(-a1, m.c1, m.c2) + cx1;
    float nc2 = fmaf(-a2, m.c1, cx2);
    m.m00 = n00; m.m01 = n01; m.m10 = n10; m.m11 = n11;
    m.c1 = nc1; m.c2 = nc2;
}

__device__ __forceinline__ float2 aff_apply(const Aff& m, float s1, float s2) {
    float t1 = m.m00 * s1 + m.m01 * s2 + m.c1;
    float t2 = m.m10 * s1 + m.m11 * s2 + m.c2;
    return make_float2(t1, t2);
}

__device__ __forceinline__ Aff aff_shfl_up(const Aff& a, int d) {
    Aff r;
    r.m00 = __shfl_up_sync(0xFFFFFFFFu, a.m00, d);
    r.m01 = __shfl_up_sync(0xFFFFFFFFu, a.m01, d);
    r.m10 = __shfl_up_sync(0xFFFFFFFFu, a.m10, d);
    r.m11 = __shfl_up_sync(0xFFFFFFFFu, a.m11, d);
    r.c1  = __shfl_up_sync(0xFFFFFFFFu, a.c1,  d);
    r.c2  = __shfl_up_sync(0xFFFFFFFFu, a.c2,  d);
    return r;
}

__device__ __forceinline__ Aff aff_shfl_down(const Aff& a, int d) {
    Aff r;
    r.m00 = __shfl_down_sync(0xFFFFFFFFu, a.m00, d);
    r.m01 = __shfl_down_sync(0xFFFFFFFFu, a.m01, d);
    r.m10 = __shfl_down_sync(0xFFFFFFFFu, a.m10, d);
    r.m11 = __shfl_down_sync(0xFFFFFFFFu, a.m11, d);
    r.c1  = __shfl_down_sync(0xFFFFFFFFu, a.c1,  d);
    r.c2  = __shfl_down_sync(0xFFFFFFFFu, a.c2,  d);
    return r;
}

// ---------------------------------------------------------------------------
// K1: coeffs + dry precompute, thread-local 8-step compose, warp reduction
//     -> one composed map per 256-sample warp chunk.
// ---------------------------------------------------------------------------
__global__ void __launch_bounds__(256) k_front(
    const float* __restrict__ w_sig,
    const float* __restrict__ q_sig,
    const float* __restrict__ midi01,
    const float* __restrict__ alpha01,
    const float* __restrict__ phase)
{
    int tid  = blockIdx.x * blockDim.x + threadIdx.x;   // 0..65535
    int lane = threadIdx.x & 31;
    int base = tid * TPS;

    // oscillator scalars (only needed for t < 6000)
    float alpha = 0.f, f0 = 0.f, ph0 = 0.f;
    if (base < 6000) {
        alpha = alpha01[0] * (3.0f - 0.2f) + 0.2f;
        float midi = rintf(midi01[0] * (60.0f - 30.0f) + 30.0f);
        f0 = 440.0f * exp2f((midi - 69.0f) / 12.0f);
        ph0 = phase[0];
    }

    Aff acc = aff_identity();

#pragma unroll
    for (int j = 0; j < TPS; j++) {
        int t = base + j;
        float tf = (float)t;

        float w_hz = w_sig[t] * 7900.0f + 100.0f;
        float qv   = q_sig[t] * (8.0f - 0.7071f) + 0.7071f;
        float w0   = (TWO_PI_F * w_hz) / 48000.0f;
        float sw, cw;
        sincosf(w0, &sw, &cw);
        float af = sw / (2.0f * qv);
        float a0 = 1.0f + af;
        float b0 = ((1.0f - cw) * 0.5f) / a0;
        float a1 = (-2.0f * cw) / a0;
        float a2 = (1.0f - af) / a0;

        float dry = 0.0f;
        if (t < 6000) {
            float eb  = 1.0f - tf / 6000.0f;
            eb        = fminf(fmaxf(eb, 0.0f), 1.0f);
            float env = powf(eb, alpha);
            float arg = ph0 + (TWO_PI_F * f0) * tf / 48000.0f;
            float u   = arg / TWO_PI_F;
            float phm = u - floorf(u);
            float sq  = (phm < 0.5f) ? 1.0f : -1.0f;
            dry = (0.5f * sq) * env;     // OSC_SHAPE=1, OSC_GAIN=0.5
        }

        g_T[t] = make_float4(b0, a1, a2, dry);
        aff_step(acc, b0, a1, a2, dry);
    }

    // ordered warp reduction: lane 0 ends with map covering all 256 samples
#pragma unroll
    for (int d = 1; d < 32; d <<= 1) {
        Aff up = aff_shfl_down(acc, d);   // covers LATER samples
        Aff comb = aff_compose(up, acc);
        acc = comb;                        // high lanes hold garbage; lane 0 correct
    }
    if (lane == 0) g_CT[tid >> 5] = acc;
}

// ---------------------------------------------------------------------------
// K2: scan 2048 warp-chunk maps -> start state of each warp chunk.
//     Single block, 256 threads x 8 maps each.
// ---------------------------------------------------------------------------
__global__ void __launch_bounds__(256) k_scan(const float* __restrict__ zi)
{
    __shared__ Aff s_tot[8];
    __shared__ Aff s_pre[8];

    int j    = threadIdx.x;        // 0..255
    int lane = j & 31;
    int wid  = j >> 5;

    Aff local[8];
    Aff acc = aff_identity();
#pragma unroll
    for (int i = 0; i < 8; i++) {
        local[i] = g_CT[j * 8 + i];
        acc = aff_compose(local[i], acc);
    }

    // warp inclusive scan (ordered Hillis-Steele)
#pragma unroll
    for (int d = 1; d < 32; d <<= 1) {
        Aff low = aff_shfl_up(acc, d);
        Aff comb = aff_compose(acc, low);
        if (lane >= d) acc = comb;
    }

    if (lane == 31) s_tot[wid] = acc;
    __syncthreads();
    if (j == 0) {
        Aff run = aff_identity();
        for (int w = 0; w < 8; w++) {
            s_pre[w] = run;
            run = aff_compose(s_tot[w], run);
        }
    }
    __syncthreads();

    // thread-exclusive map = laneExclusive ∘ warpExclusive
    Aff ex = aff_shfl_up(acc, 1);
    if (lane == 0) ex = aff_identity();
    Aff thrEx = aff_compose(ex, s_pre[wid]);

    float2 s = aff_apply(thrEx, zi[0], zi[1]);
#pragma unroll
    for (int i = 0; i < 8; i++) {
        g_S[j * 8 + i] = s;
        s = aff_apply(local[i], s.x, s.y);
    }
}

// ---------------------------------------------------------------------------
// K3: thread compose + warp exclusive scan -> per-thread start state,
//     then exact reference DF2T replay of 8 samples + tanh.
// ---------------------------------------------------------------------------
__global__ void __launch_bounds__(256) k_replay(float* __restrict__ out)
{
    int tid  = blockIdx.x * blockDim.x + threadIdx.x;
    int lane = threadIdx.x & 31;
    int wg   = tid >> 5;            // warp-chunk index
    int base = tid * TPS;

    Aff acc = aff_identity();
#pragma unroll
    for (int j = 0; j < TPS; j++) {
        float4 T = g_T[base + j];
        aff_step(acc, T.x, T.y, T.z, T.w);
    }

    // warp inclusive scan
#pragma unroll
    for (int d = 1; d < 32; d <<= 1) {
        Aff low = aff_shfl_up(acc, d);
        Aff comb = aff_compose(acc, low);
        if (lane >= d) acc = comb;
    }
    // exclusive
    Aff ex = aff_shfl_up(acc, 1);
    if (lane == 0) ex = aff_identity();

    float2 sw = g_S[wg];
    float2 s  = aff_apply(ex, sw.x, sw.y);
    float s1 = s.x, s2 = s.y;

    float buf[TPS];
#pragma unroll
    for (int j = 0; j < TPS; j++) {
        float4 T = g_T[base + j];       // L1 hit (loaded above)
        float b0 = T.x, a1 = T.y, a2 = T.z, x = T.w;
        float p0 = b0 * x;
        float y  = p0 + s1;                        // y  = b0*x + s1
        float ns1 = fmaf(-a1, y, 2.0f * p0) + s2;  // s1 = b1*x - a1*y + s2
        float ns2 = fmaf(-a2, y, p0);              // s2 = b2*x - a2*y
        s1 = ns1; s2 = ns2;
        buf[j] = tanhf(y);                         // DIST_GAIN = 1
    }

    float4* o4 = (float4*)(out + base);
    o4[0] = make_float4(buf[0], buf[1], buf[2], buf[3]);
    o4[1] = make_float4(buf[4], buf[5], buf[6], buf[7]);
}

// ---------------------------------------------------------------------------
// Inputs (metadata order): x, midi_f0_0to1, alpha_0to1, w_mod_sig, q_mod_sig,
//                          phase, zi. Output: wet [1, N] float32.
// ---------------------------------------------------------------------------
extern "C" void kernel_launch(void* const* d_in, const int* in_sizes, int n_in,
                              void* d_out, int out_size)
{
    const float* midi  = (const float*)d_in[1];
    const float* alpha = (const float*)d_in[2];
    const float* w     = (const float*)d_in[3];
    const float* q     = (const float*)d_in[4];
    const float* phase = (const float*)d_in[5];
    const float* zi    = (const float*)d_in[6];
    float* out = (float*)d_out;

    k_front <<<NTHREAD / 256, 256>>>(w, q, midi, alpha, phase);
    k_scan  <<<1, 256>>>(zi);
    k_replay<<<NTHREAD / 256, 256>>>(out);
}